// round 1
// baseline (speedup 1.0000x reference)
#include <cuda_runtime.h>
#include <math.h>

#define BB 64
#define SS 512
#define CC 1024
#define HH 1024
#define G3 3072   // 3*H

// ---------------- scratch (static device globals; no runtime allocation) ----------------
__device__ float d_g0[(size_t)SS * BB * G3];   // precomputed layer-0 input projections (+b_ih0)
__device__ float d_h0[2][BB * HH];             // double-buffered layer-0 hidden
__device__ float d_h1[2][BB * HH];             // double-buffered layer-1 hidden
__device__ float d_gh1[BB * G3];               // layer-1 recurrent gates buffer, packed (hc*3+g)
__device__ unsigned int d_bar_arrive;
__device__ unsigned int d_bar_gen;

// ---------------- grid-wide barrier (sense-reversing via generation counter) ----------------
__device__ __forceinline__ void grid_sync(int nblocks) {
    __syncthreads();
    if (threadIdx.x == 0) {
        __threadfence();  // publish our writes (also CCTL.IVALL -> L1 invalidate on this arch)
        unsigned int gen = *((volatile unsigned int*)&d_bar_gen);
        if (atomicAdd(&d_bar_arrive, 1u) == (unsigned int)(nblocks - 1)) {
            atomicExch(&d_bar_arrive, 0u);
            __threadfence();
            atomicExch(&d_bar_gen, gen + 1u);
        } else {
            while (*((volatile unsigned int*)&d_bar_gen) == gen) { __nanosleep(64); }
        }
        __threadfence();  // acquire: invalidate L1 before consuming others' writes
    }
    __syncthreads();
}

__device__ __forceinline__ float sigmoidf_(float x) {
    return 1.0f / (1.0f + __expf(-x));
}

// ======================= Phase A: gi0 = x @ W_ih0^T + b_ih0 ===========================
// C tile: 64 rows (batch) x 64 cols. Row index in d_g0 is (t*64 + b).
__global__ __launch_bounds__(256) void gru_phaseA(const float* __restrict__ x,
                                                  const float* __restrict__ wih0,
                                                  const float* __restrict__ bih0) {
    __shared__ __align__(16) float As[16][68];
    __shared__ __align__(16) float Bs[16][68];
    const int t    = blockIdx.x;   // 0..511
    const int nblk = blockIdx.y;   // 0..47
    const int tid  = threadIdx.x;
    const int lr = tid >> 2, lq = tid & 3;     // loader: row 0..63, quad 0..3
    const int tx = tid & 15, ty = tid >> 4;    // compute: 4 rows x 4 cols micro-tile

    float acc[4][4];
#pragma unroll
    for (int i = 0; i < 4; i++)
#pragma unroll
        for (int j = 0; j < 4; j++) acc[i][j] = 0.0f;

    const float* xrow = x + ((size_t)lr * SS + t) * CC;            // batch row lr, time t
    const float* wrow = wih0 + (size_t)(nblk * 64 + lr) * CC;

    float4 av = *(const float4*)(xrow + lq * 4);
    float4 bv = *(const float4*)(wrow + lq * 4);

    for (int k0 = 0; k0 < CC; k0 += 16) {
        __syncthreads();
        As[lq*4+0][lr] = av.x; As[lq*4+1][lr] = av.y; As[lq*4+2][lr] = av.z; As[lq*4+3][lr] = av.w;
        Bs[lq*4+0][lr] = bv.x; Bs[lq*4+1][lr] = bv.y; Bs[lq*4+2][lr] = bv.z; Bs[lq*4+3][lr] = bv.w;
        __syncthreads();
        if (k0 + 16 < CC) {  // prefetch next chunk
            av = *(const float4*)(xrow + k0 + 16 + lq * 4);
            bv = *(const float4*)(wrow + k0 + 16 + lq * 4);
        }
#pragma unroll
        for (int kk = 0; kk < 16; kk++) {
            float4 a = *(const float4*)&As[kk][tx * 4];
            float4 b = *(const float4*)&Bs[kk][ty * 4];
            float ar[4] = {a.x, a.y, a.z, a.w};
            float br[4] = {b.x, b.y, b.z, b.w};
#pragma unroll
            for (int i = 0; i < 4; i++)
#pragma unroll
                for (int j = 0; j < 4; j++) acc[i][j] += ar[i] * br[j];
        }
    }

    const int colb = nblk * 64 + ty * 4;
    float4 bias4 = *(const float4*)(bih0 + colb);
#pragma unroll
    for (int i = 0; i < 4; i++) {
        size_t m = (size_t)t * 64 + tx * 4 + i;
        float4 o;
        o.x = acc[i][0] + bias4.x;
        o.y = acc[i][1] + bias4.y;
        o.z = acc[i][2] + bias4.z;
        o.w = acc[i][3] + bias4.w;
        *(float4*)(d_g0 + m * G3 + colb) = o;
    }
}

// ======================= Phase B job: one hcol tile (16 cols -> 48 gate cols) =================
// MODE 0: layer0 gh + gates -> h0_new  (ih-part from d_g0)
// MODE 1: layer1 gh + b_hh  -> d_gh1   (raw, packed hc*3+g)
// MODE 2: layer1 gi + gates -> h1_new  (hh-part from d_gh1)
template <int MODE>
__device__ __forceinline__ void gru_job(int t, int c0,
                                        const float* __restrict__ hA,
                                        const float* __restrict__ W,
                                        const float* __restrict__ bias,
                                        const float* __restrict__ hprev,
                                        float* __restrict__ hout,
                                        float (&As)[16][68], float (&Bs)[16][52]) {
    const int tid = threadIdx.x;
    const int lr = tid >> 2, lq = tid & 3;
    const int tx = tid & 15, ty = tid >> 4;   // thread owns rows 4tx..4tx+3, hidden col c0+ty

    float acc[4][3];
#pragma unroll
    for (int i = 0; i < 4; i++) { acc[i][0] = 0.f; acc[i][1] = 0.f; acc[i][2] = 0.f; }

    const float* arow = hA + (size_t)lr * HH;
    const float* wrow = nullptr;
    if (lr < 48) {
        int g  = lr % 3;        // gate (r,z,n)
        int hc = lr / 3;        // local hidden col
        wrow = W + (size_t)(g * HH + c0 + hc) * CC;
    }

    float4 av = *(const float4*)(arow + lq * 4);
    float4 bv = make_float4(0.f, 0.f, 0.f, 0.f);
    if (lr < 48) bv = *(const float4*)(wrow + lq * 4);

    for (int k0 = 0; k0 < CC; k0 += 16) {
        __syncthreads();
        As[lq*4+0][lr] = av.x; As[lq*4+1][lr] = av.y; As[lq*4+2][lr] = av.z; As[lq*4+3][lr] = av.w;
        if (lr < 48) {
            Bs[lq*4+0][lr] = bv.x; Bs[lq*4+1][lr] = bv.y; Bs[lq*4+2][lr] = bv.z; Bs[lq*4+3][lr] = bv.w;
        }
        __syncthreads();
        if (k0 + 16 < CC) {
            av = *(const float4*)(arow + k0 + 16 + lq * 4);
            if (lr < 48) bv = *(const float4*)(wrow + k0 + 16 + lq * 4);
        }
#pragma unroll
        for (int kk = 0; kk < 16; kk++) {
            float4 a = *(const float4*)&As[kk][tx * 4];
            float b0 = Bs[kk][ty * 3 + 0];
            float b1 = Bs[kk][ty * 3 + 1];
            float b2 = Bs[kk][ty * 3 + 2];
            acc[0][0] += a.x * b0; acc[0][1] += a.x * b1; acc[0][2] += a.x * b2;
            acc[1][0] += a.y * b0; acc[1][1] += a.y * b1; acc[1][2] += a.y * b2;
            acc[2][0] += a.z * b0; acc[2][1] += a.z * b1; acc[2][2] += a.z * b2;
            acc[3][0] += a.w * b0; acc[3][1] += a.w * b1; acc[3][2] += a.w * b2;
        }
    }

    const int hc = c0 + ty;
    const float b_r = bias[hc], b_z = bias[HH + hc], b_n = bias[2 * HH + hc];

    if (MODE == 1) {
#pragma unroll
        for (int i = 0; i < 4; i++) {
            int row = tx * 4 + i;
            float* p = d_gh1 + (size_t)row * G3 + hc * 3;
            p[0] = acc[i][0] + b_r;
            p[1] = acc[i][1] + b_z;
            p[2] = acc[i][2] + b_n;
        }
    } else if (MODE == 0) {
#pragma unroll
        for (int i = 0; i < 4; i++) {
            int row = tx * 4 + i;
            const float* g0p = d_g0 + ((size_t)t * BB + row) * G3;
            float i_r = g0p[hc], i_z = g0p[HH + hc], i_n = g0p[2 * HH + hc];
            float h_r = acc[i][0] + b_r;
            float h_z = acc[i][1] + b_z;
            float h_n = acc[i][2] + b_n;
            float r = sigmoidf_(i_r + h_r);
            float z = sigmoidf_(i_z + h_z);
            float n = tanhf(i_n + r * h_n);
            float hp = hprev[(size_t)row * HH + hc];
            hout[(size_t)row * HH + hc] = (1.f - z) * n + z * hp;
        }
    } else {  // MODE 2
#pragma unroll
        for (int i = 0; i < 4; i++) {
            int row = tx * 4 + i;
            const float* p = d_gh1 + (size_t)row * G3 + hc * 3;
            float h_r = p[0], h_z = p[1], h_n = p[2];
            float i_r = acc[i][0] + b_r;
            float i_z = acc[i][1] + b_z;
            float i_n = acc[i][2] + b_n;
            float r = sigmoidf_(i_r + h_r);
            float z = sigmoidf_(i_z + h_z);
            float n = tanhf(i_n + r * h_n);
            float hp = hprev[(size_t)row * HH + hc];
            hout[(size_t)row * HH + hc] = (1.f - z) * n + z * hp;
        }
    }
}

// ======================= Phase B: persistent sequential recurrence =======================
__global__ __launch_bounds__(256) void gru_phaseB(const float* __restrict__ wih,
                                                  const float* __restrict__ whh,
                                                  const float* __restrict__ bih,
                                                  const float* __restrict__ bhh,
                                                  float* __restrict__ out) {
    __shared__ __align__(16) float As[16][68];
    __shared__ __align__(16) float Bs[16][52];
    const int nb = gridDim.x;
    const int tid = threadIdx.x;

    // zero-init h states (buffer 0)
    for (int i = blockIdx.x * blockDim.x + tid; i < BB * HH; i += nb * blockDim.x) {
        d_h0[0][i] = 0.f;
        d_h1[0][i] = 0.f;
    }
    grid_sync(nb);

    for (int t = 0; t < SS; t++) {
        const int cur = t & 1, nxt = cur ^ 1;

        // Stage 1: layer0 full update (jobs 0..63) + layer1 recurrent gemm (jobs 64..127)
        for (int job = blockIdx.x; job < 128; job += nb) {
            const int c0 = (job & 63) * 16;
            if (job < 64)
                gru_job<0>(t, c0, d_h0[cur], whh, bhh, d_h0[cur], d_h0[nxt], As, Bs);
            else
                gru_job<1>(t, c0, d_h1[cur], whh + (size_t)G3 * HH, bhh + G3,
                           nullptr, nullptr, As, Bs);
        }
        grid_sync(nb);

        // Stage 2: layer1 input gemm (from fresh h0) + gates
        for (int job = blockIdx.x; job < 64; job += nb) {
            const int c0 = job * 16;
            gru_job<2>(t, c0, d_h0[nxt], wih + (size_t)G3 * CC, bih + G3,
                       d_h1[cur], d_h1[nxt], As, Bs);
        }
        grid_sync(nb);
    }

    // final hidden of layer 1 lives in buffer (SS & 1) ^ 1 ... after t=511: written to buffer 0
    for (int i = blockIdx.x * blockDim.x + tid; i < BB * HH; i += nb * blockDim.x)
        out[i] = d_h1[0][i];
}

// ================================= host launcher =================================
extern "C" void kernel_launch(void* const* d_in, const int* in_sizes, int n_in,
                              void* d_out, int out_size) {
    const float* x   = (const float*)d_in[0];  // [64, 512, 1024]
    const float* wih = (const float*)d_in[1];  // [2, 3072, 1024]
    const float* whh = (const float*)d_in[2];  // [2, 3072, 1024]
    const float* bih = (const float*)d_in[3];  // [2, 3072]
    const float* bhh = (const float*)d_in[4];  // [2, 3072]
    float* out = (float*)d_out;                // [64, 1024]

    int nsm = 0;
    cudaDeviceGetAttribute(&nsm, cudaDevAttrMultiProcessorCount, 0);
    if (nsm <= 0) nsm = 132;  // conservative fallback

    dim3 ga(SS, G3 / 64);
    gru_phaseA<<<ga, 256>>>(x, wih, bih);
    gru_phaseB<<<nsm, 256>>>(wih, whh, bih, bhh, out);
}